// round 2
// baseline (speedup 1.0000x reference)
#include <cuda_runtime.h>

typedef unsigned long long ull;

#define SEQ   512
#define HD    64
#define G4    256          // 4*H
#define ROWS  16           // batch rows per CTA
#define NCTA  128          // 2048 / 16
#define NTHR  512
#define OUTF  72
#define XP    18           // Xd pitch in ull (bank-conflict break)

// SMEM: W0s[64][256] f32 (gate-interleaved) | W1s[128][256] f32 | Xd[128][XP] u64
#define SMEM_BYTES ((64*256 + 128*256)*4 + 128*XP*8)   // 215040

__device__ __forceinline__ ull pack2(float a, float b) {
    ull r; asm("mov.b64 %0, {%1, %2};" : "=l"(r) : "f"(a), "f"(b)); return r;
}
__device__ __forceinline__ void unpack2(ull v, float &a, float &b) {
    asm("mov.b64 {%0, %1}, %2;" : "=f"(a), "=f"(b) : "l"(v));
}
__device__ __forceinline__ void fma2(ull &d, ull a, ull b) {
    // packed fp32x2 FMA (sm_100+): d = a*b + d, elementwise on the two f32 lanes
    asm("fma.rn.f32x2 %0, %1, %2, %0;" : "+l"(d) : "l"(a), "l"(b));
}
__device__ __forceinline__ float sigf(float x) {
    return __fdividef(1.0f, 1.0f + __expf(-x));
}
__device__ __forceinline__ float tanhf_(float x) {
    float e = __expf(-2.0f * fabsf(x));
    float r = __fdividef(1.0f - e, 1.0f + e);
    return copysignf(r, x);
}

// one row's LSTM cell update from packed gate accumulators; returns h
__device__ __forceinline__ float cell_update(ull aIF, ull aGO, float &c) {
    float gi, gf, gg, go;
    unpack2(aIF, gi, gf);
    unpack2(aGO, gg, go);
    float i = sigf(gi), f = sigf(gf), g = tanhf_(gg), o = sigf(go);
    c = f * c + i * g;
    return o * tanhf_(c);
}

__global__ __launch_bounds__(NTHR, 1)
void lstm_forecaster_kernel(const float* __restrict__ x,
                            const float* __restrict__ Wih0,
                            const float* __restrict__ Whh0,
                            const float* __restrict__ bih0,
                            const float* __restrict__ bhh0,
                            const float* __restrict__ Wih1,
                            const float* __restrict__ Whh1,
                            const float* __restrict__ bih1,
                            const float* __restrict__ bhh1,
                            const float* __restrict__ fcw,
                            const float* __restrict__ fcb,
                            float* __restrict__ out)
{
    extern __shared__ float sm[];
    float* W0s = sm;                          // [64][256]  gate-interleaved, k-major
    float* W1s = sm + 64 * G4;                // [128][256] k<64: Wih1, k>=64: Whh1
    ull*   Xd  = (ull*)(sm + (64 + 128) * G4);// [128][XP]: k<64 h0 dup, k>=64 h1 dup

    const int tid = threadIdx.x;
    const int j   = tid >> 3;                 // cell index 0..63 (4 gate cols)
    const int rp  = tid & 7;                  // row-pair index 0..7
    const int rp2 = rp << 1;                  // row r0 = rp2, r1 = rp2+1
    const int jc4 = j << 2;                   // first gate col of this cell

    // ---- load weights into shared, gate-interleaved: col' = j*4 + gate ----
    // original row index of (gate g, cell j) = g*64 + j
    for (int idx = tid; idx < 64 * G4; idx += NTHR) {
        int k = idx >> 8, col = idx & 255;
        int jj = col >> 2, g = col & 3;
        W0s[idx] = Whh0[(g * HD + jj) * HD + k];
    }
    for (int idx = tid; idx < 128 * G4; idx += NTHR) {
        int k = idx >> 8, col = idx & 255;
        int jj = col >> 2, g = col & 3;
        W1s[idx] = (k < HD) ? Wih1[(g * HD + jj) * HD + k]
                            : Whh1[(g * HD + jj) * HD + (k - HD)];
    }
    for (int idx = tid; idx < 128 * XP; idx += NTHR) Xd[idx] = 0ull;

    // ---- per-thread constants: gate-pair packed weights/biases for cell j ----
    // IF lanes = gates (i,f) = rows j, j+64 ; GO lanes = (g,o) = rows j+128, j+192
    ull w0if = pack2(Wih0[j],          Wih0[j + HD]);
    ull w0go = pack2(Wih0[j + 2*HD],   Wih0[j + 3*HD]);
    ull b0if = pack2(bih0[j] + bhh0[j],               bih0[j + HD] + bhh0[j + HD]);
    ull b0go = pack2(bih0[j + 2*HD] + bhh0[j + 2*HD], bih0[j + 3*HD] + bhh0[j + 3*HD]);
    ull b1if = pack2(bih1[j] + bhh1[j],               bih1[j + HD] + bhh1[j + HD]);
    ull b1go = pack2(bih1[j + 2*HD] + bhh1[j + 2*HD], bih1[j + 3*HD] + bhh1[j + 3*HD]);

    float c00 = 0.f, c01 = 0.f;   // layer-0 cell state, rows r0/r1
    float c10 = 0.f, c11 = 0.f;   // layer-1 cell state

    const int gRow = blockIdx.x * ROWS;

    float xr0 = x[(gRow + rp2 + 0) * SEQ];
    float xr1 = x[(gRow + rp2 + 1) * SEQ];

    __syncthreads();

    for (int s = 0; s < SEQ; ++s) {
        // ============ layer 0: gates = b0 + x*wih0 + h0 @ Whh0^T ============
        ull aIF0 = b0if, aGO0 = b0go, aIF1 = b0if, aGO1 = b0go;
        {
            ull xx0 = pack2(xr0, xr0), xx1 = pack2(xr1, xr1);
            fma2(aIF0, xx0, w0if); fma2(aGO0, xx0, w0go);
            fma2(aIF1, xx1, w0if); fma2(aGO1, xx1, w0go);
        }
        // prefetch next x (hidden under GEMM)
        int sn = (s + 1 < SEQ) ? (s + 1) : s;
        float xn0 = x[(gRow + rp2 + 0) * SEQ + sn];
        float xn1 = x[(gRow + rp2 + 1) * SEQ + sn];

        #pragma unroll 8
        for (int k = 0; k < HD; ++k) {
            ulonglong2 hv = *(const ulonglong2*)&Xd[k * XP + rp2];
            ulonglong2 wv = *(const ulonglong2*)&W0s[k * G4 + jc4];
            fma2(aIF0, hv.x, wv.x); fma2(aGO0, hv.x, wv.y);
            fma2(aIF1, hv.y, wv.x); fma2(aGO1, hv.y, wv.y);
        }
        xr0 = xn0; xr1 = xn1;
        __syncthreads();   // all h0 reads done before overwrite (WAR)

        // ============ layer 0 state update (in registers) ============
        {
            float h0 = cell_update(aIF0, aGO0, c00);
            float h1 = cell_update(aIF1, aGO1, c01);
            *(ulonglong2*)&Xd[j * XP + rp2] = make_ulonglong2(pack2(h0, h0), pack2(h1, h1));
        }
        __syncthreads();   // h0 visible before layer-1 GEMM

        // ============ layer 1: gates = b1 + [h0,h1] @ [Wih1;Whh1]^T ============
        aIF0 = b1if; aGO0 = b1go; aIF1 = b1if; aGO1 = b1go;
        #pragma unroll 8
        for (int k = 0; k < 2 * HD; ++k) {
            ulonglong2 hv = *(const ulonglong2*)&Xd[k * XP + rp2];
            ulonglong2 wv = *(const ulonglong2*)&W1s[k * G4 + jc4];
            fma2(aIF0, hv.x, wv.x); fma2(aGO0, hv.x, wv.y);
            fma2(aIF1, hv.y, wv.x); fma2(aGO1, hv.y, wv.y);
        }
        __syncthreads();   // all h1 reads done before overwrite (WAR)

        // ============ layer 1 state update ============
        {
            float h0 = cell_update(aIF0, aGO0, c10);
            float h1 = cell_update(aIF1, aGO1, c11);
            *(ulonglong2*)&Xd[(HD + j) * XP + rp2] = make_ulonglong2(pack2(h0, h0), pack2(h1, h1));
        }
        // no barrier here: next layer-0 GEMM reads only Xd[0:64];
        // h1 store is protected by the two barriers before next layer-1 GEMM.
    }

    __syncthreads();

    // ============ final FC: out = h1_last @ fcw^T + fcb ============
    const float* XdF = (const float*)Xd;
    for (int idx = tid; idx < ROWS * OUTF; idx += NTHR) {
        int r = idx / OUTF;
        int o = idx - r * OUTF;
        float acc = fcb[o];
        #pragma unroll 16
        for (int k = 0; k < HD; ++k) {
            float h = XdF[((HD + k) * XP + r) * 2];   // low half of dup pair
            acc = fmaf(h, fcw[o * HD + k], acc);
        }
        out[(gRow + r) * OUTF + o] = acc;
    }
}

extern "C" void kernel_launch(void* const* d_in, const int* in_sizes, int n_in,
                              void* d_out, int out_size)
{
    (void)in_sizes; (void)n_in; (void)out_size;
    cudaFuncSetAttribute(lstm_forecaster_kernel,
                         cudaFuncAttributeMaxDynamicSharedMemorySize, SMEM_BYTES);
    lstm_forecaster_kernel<<<NCTA, NTHR, SMEM_BYTES>>>(
        (const float*)d_in[0],   // x
        (const float*)d_in[1],   // W_ih_l0
        (const float*)d_in[2],   // W_hh_l0
        (const float*)d_in[3],   // b_ih_l0
        (const float*)d_in[4],   // b_hh_l0
        (const float*)d_in[5],   // W_ih_l1
        (const float*)d_in[6],   // W_hh_l1
        (const float*)d_in[7],   // b_ih_l1
        (const float*)d_in[8],   // b_hh_l1
        (const float*)d_in[9],   // fc_w
        (const float*)d_in[10],  // fc_b
        (float*)d_out);
}

// round 3
// speedup vs baseline: 1.4611x; 1.4611x over previous
#include <cuda_runtime.h>

typedef unsigned long long ull;

#define SEQ   512
#define HD    64
#define G4    256          // 4*H
#define ROWS  16           // batch rows per CTA
#define NCTA  128          // 2048 / 16
#define NTHR  256
#define OUTF  72
#define XP    18           // Xd pitch in ull (16B-aligned, bank-rotating)

// SMEM: W0s[64][256] | W1s[128][256] (both f32, gate-interleaved cols)
//       Xd: h0 buf0 [64][XP] | h0 buf1 [64][XP] | h1 [64][XP]  (dup-packed ull)
#define SMEM_BYTES ((64*G4 + 128*G4)*4 + 3*64*XP*8)   // 224256

__device__ __forceinline__ ull pack2(float a, float b) {
    ull r; asm("mov.b64 %0, {%1, %2};" : "=l"(r) : "f"(a), "f"(b)); return r;
}
__device__ __forceinline__ void unpack2(ull v, float &a, float &b) {
    asm("mov.b64 {%0, %1}, %2;" : "=f"(a), "=f"(b) : "l"(v));
}
__device__ __forceinline__ void fma2(ull &d, ull a, ull b) {
    // packed fp32x2 FMA (sm_100+): d = a*b + d elementwise
    asm("fma.rn.f32x2 %0, %1, %2, %0;" : "+l"(d) : "l"(a), "l"(b));
}
__device__ __forceinline__ float sigf(float x) {
    return __fdividef(1.0f, 1.0f + __expf(-x));
}
__device__ __forceinline__ float tanhf_(float x) {
    float e = __expf(-2.0f * fabsf(x));
    float r = __fdividef(1.0f - e, 1.0f + e);
    return copysignf(r, x);
}
// gates packed: aIF = (i,f), aGO = (g,o); updates c, returns h
__device__ __forceinline__ float cell_update(ull aIF, ull aGO, float &c) {
    float gi, gf, gg, go;
    unpack2(aIF, gi, gf);
    unpack2(aGO, gg, go);
    float i = sigf(gi), f = sigf(gf), g = tanhf_(gg), o = sigf(go);
    c = f * c + i * g;
    return o * tanhf_(c);
}

__global__ __launch_bounds__(NTHR, 1)
void lstm_forecaster_kernel(const float* __restrict__ x,
                            const float* __restrict__ Wih0,
                            const float* __restrict__ Whh0,
                            const float* __restrict__ bih0,
                            const float* __restrict__ bhh0,
                            const float* __restrict__ Wih1,
                            const float* __restrict__ Whh1,
                            const float* __restrict__ bih1,
                            const float* __restrict__ bhh1,
                            const float* __restrict__ fcw,
                            const float* __restrict__ fcb,
                            float* __restrict__ out)
{
    extern __shared__ float sm[];
    float* W0s = sm;                           // [64][256]  gate-interleaved, k-major
    float* W1s = sm + 64 * G4;                 // [128][256] k<64: Wih1, k>=64: Whh1
    ull*   Xd  = (ull*)(sm + (64 + 128) * G4); // 3 regions of [64][XP]

    const int tid  = threadIdx.x;
    const int warp = tid >> 5, lane = tid & 31;
    const int rr   = lane >> 3;               // row-group 0..3
    const int gg   = lane & 7;                // cell-within-warp 0..7
    const int j    = warp * 8 + gg;           // cell index 0..63
    const int jc4  = j << 2;                  // first interleaved col of cell j
    const int gr0  = rr << 2;                 // first of 4 rows

    // ---- weights into shared, gate-interleaved: col' = cell*4 + gate ----
    for (int idx = tid; idx < 64 * G4; idx += NTHR) {
        int k = idx >> 8, col = idx & 255;
        int jj = col >> 2, g = col & 3;
        W0s[idx] = Whh0[(g * HD + jj) * HD + k];
    }
    for (int idx = tid; idx < 128 * G4; idx += NTHR) {
        int k = idx >> 8, col = idx & 255;
        int jj = col >> 2, g = col & 3;
        W1s[idx] = (k < HD) ? Wih1[(g * HD + jj) * HD + k]
                            : Whh1[(g * HD + jj) * HD + (k - HD)];
    }
    for (int idx = tid; idx < 3 * 64 * XP; idx += NTHR) Xd[idx] = 0ull;

    // ---- per-thread constants for cell j ----
    ull w0if = pack2(Wih0[j],          Wih0[j + HD]);
    ull w0go = pack2(Wih0[j + 2*HD],   Wih0[j + 3*HD]);
    ull b0if = pack2(bih0[j] + bhh0[j],               bih0[j + HD] + bhh0[j + HD]);
    ull b0go = pack2(bih0[j + 2*HD] + bhh0[j + 2*HD], bih0[j + 3*HD] + bhh0[j + 3*HD]);
    ull b1if = pack2(bih1[j] + bhh1[j],               bih1[j + HD] + bhh1[j + HD]);
    ull b1go = pack2(bih1[j + 2*HD] + bhh1[j + 2*HD], bih1[j + 3*HD] + bhh1[j + 3*HD]);

    float c0[4] = {0.f, 0.f, 0.f, 0.f};
    float c1[4] = {0.f, 0.f, 0.f, 0.f};

    // h0 double buffers + h1 region
    ull* X0a = Xd + 64 * XP;   // read at s=0 (zeros)
    ull* X0b = Xd;             // written at s=0
    ull* X1  = Xd + 2 * 64 * XP;

    const int gRow = blockIdx.x * ROWS;

    float xr0 = x[(gRow + gr0 + 0) * SEQ];
    float xr1 = x[(gRow + gr0 + 1) * SEQ];
    float xr2 = x[(gRow + gr0 + 2) * SEQ];
    float xr3 = x[(gRow + gr0 + 3) * SEQ];

    __syncthreads();

    for (int s = 0; s < SEQ; ++s) {
        ull* X0r = X0a;   // holds h0(s-1)
        ull* X0w = X0b;   // receives h0(s)

        // ============ layer 0 GEMM: gates = b0 + x*wih0 + h0(s-1) @ Whh0^T ============
        ull aIF0 = b0if, aGO0 = b0go, aIF1 = b0if, aGO1 = b0go;
        ull aIF2 = b0if, aGO2 = b0go, aIF3 = b0if, aGO3 = b0go;
        {
            ull xx0 = pack2(xr0, xr0), xx1 = pack2(xr1, xr1);
            ull xx2 = pack2(xr2, xr2), xx3 = pack2(xr3, xr3);
            fma2(aIF0, xx0, w0if); fma2(aGO0, xx0, w0go);
            fma2(aIF1, xx1, w0if); fma2(aGO1, xx1, w0go);
            fma2(aIF2, xx2, w0if); fma2(aGO2, xx2, w0go);
            fma2(aIF3, xx3, w0if); fma2(aGO3, xx3, w0go);
        }
        // prefetch next x under the GEMM
        int sn = (s + 1 < SEQ) ? (s + 1) : s;
        float xn0 = x[(gRow + gr0 + 0) * SEQ + sn];
        float xn1 = x[(gRow + gr0 + 1) * SEQ + sn];
        float xn2 = x[(gRow + gr0 + 2) * SEQ + sn];
        float xn3 = x[(gRow + gr0 + 3) * SEQ + sn];

        #pragma unroll 8
        for (int k = 0; k < HD; ++k) {
            ulonglong2 hA = *(const ulonglong2*)&X0r[k * XP + gr0];
            ulonglong2 hB = *(const ulonglong2*)&X0r[k * XP + gr0 + 2];
            ulonglong2 wv = *(const ulonglong2*)&W0s[k * G4 + jc4];
            fma2(aIF0, hA.x, wv.x); fma2(aGO0, hA.x, wv.y);
            fma2(aIF1, hA.y, wv.x); fma2(aGO1, hA.y, wv.y);
            fma2(aIF2, hB.x, wv.x); fma2(aGO2, hB.x, wv.y);
            fma2(aIF3, hB.y, wv.x); fma2(aGO3, hB.y, wv.y);
        }
        xr0 = xn0; xr1 = xn1; xr2 = xn2; xr3 = xn3;

        // ============ layer 0 state update (registers) -> h0(s) into X0w ============
        // No barrier needed before the store: X0w != X0r (double buffer), and the
        // last readers of X0w were two barriers ago.
        {
            float h0 = cell_update(aIF0, aGO0, c0[0]);
            float h1 = cell_update(aIF1, aGO1, c0[1]);
            float h2 = cell_update(aIF2, aGO2, c0[2]);
            float h3 = cell_update(aIF3, aGO3, c0[3]);
            *(ulonglong2*)&X0w[j * XP + gr0]     = make_ulonglong2(pack2(h0, h0), pack2(h1, h1));
            *(ulonglong2*)&X0w[j * XP + gr0 + 2] = make_ulonglong2(pack2(h2, h2), pack2(h3, h3));
        }
        __syncthreads();   // h0(s) visible to all; also orders h1(s-1) stores before L1 reads

        // ============ layer 1 GEMM: gates = b1 + h0(s)@Wih1^T + h1(s-1)@Whh1^T ============
        aIF0 = b1if; aGO0 = b1go; aIF1 = b1if; aGO1 = b1go;
        aIF2 = b1if; aGO2 = b1go; aIF3 = b1if; aGO3 = b1go;
        #pragma unroll 8
        for (int k = 0; k < HD; ++k) {
            ulonglong2 hA = *(const ulonglong2*)&X0w[k * XP + gr0];
            ulonglong2 hB = *(const ulonglong2*)&X0w[k * XP + gr0 + 2];
            ulonglong2 wv = *(const ulonglong2*)&W1s[k * G4 + jc4];
            fma2(aIF0, hA.x, wv.x); fma2(aGO0, hA.x, wv.y);
            fma2(aIF1, hA.y, wv.x); fma2(aGO1, hA.y, wv.y);
            fma2(aIF2, hB.x, wv.x); fma2(aGO2, hB.x, wv.y);
            fma2(aIF3, hB.y, wv.x); fma2(aGO3, hB.y, wv.y);
        }
        #pragma unroll 8
        for (int k = 0; k < HD; ++k) {
            ulonglong2 hA = *(const ulonglong2*)&X1[k * XP + gr0];
            ulonglong2 hB = *(const ulonglong2*)&X1[k * XP + gr0 + 2];
            ulonglong2 wv = *(const ulonglong2*)&W1s[(HD + k) * G4 + jc4];
            fma2(aIF0, hA.x, wv.x); fma2(aGO0, hA.x, wv.y);
            fma2(aIF1, hA.y, wv.x); fma2(aGO1, hA.y, wv.y);
            fma2(aIF2, hB.x, wv.x); fma2(aGO2, hB.x, wv.y);
            fma2(aIF3, hB.y, wv.x); fma2(aGO3, hB.y, wv.y);
        }
        __syncthreads();   // WAR: all h1(s-1) reads done before overwrite

        // ============ layer 1 state update -> h1(s) into X1 ============
        // MUFU chain + store; next iteration's L0 GEMM (disjoint region) can
        // overlap — no barrier until the h0-visibility barrier of step s+1.
        {
            float h0 = cell_update(aIF0, aGO0, c1[0]);
            float h1 = cell_update(aIF1, aGO1, c1[1]);
            float h2 = cell_update(aIF2, aGO2, c1[2]);
            float h3 = cell_update(aIF3, aGO3, c1[3]);
            *(ulonglong2*)&X1[j * XP + gr0]     = make_ulonglong2(pack2(h0, h0), pack2(h1, h1));
            *(ulonglong2*)&X1[j * XP + gr0 + 2] = make_ulonglong2(pack2(h2, h2), pack2(h3, h3));
        }

        // swap h0 buffers
        ull* t = X0a; X0a = X0b; X0b = t;
    }

    __syncthreads();

    // ============ final FC: out = h1_last @ fcw^T + fcb ============
    const float* H1 = (const float*)(Xd + 2 * 64 * XP);
    for (int idx = tid; idx < ROWS * OUTF; idx += NTHR) {
        int r = idx / OUTF;
        int o = idx - r * OUTF;
        float acc = fcb[o];
        #pragma unroll 16
        for (int k = 0; k < HD; ++k) {
            float h = H1[(k * XP + r) * 2];   // low half of dup pair
            acc = fmaf(h, fcw[o * HD + k], acc);
        }
        out[(gRow + r) * OUTF + o] = acc;
    }
}

extern "C" void kernel_launch(void* const* d_in, const int* in_sizes, int n_in,
                              void* d_out, int out_size)
{
    (void)in_sizes; (void)n_in; (void)out_size;
    cudaFuncSetAttribute(lstm_forecaster_kernel,
                         cudaFuncAttributeMaxDynamicSharedMemorySize, SMEM_BYTES);
    lstm_forecaster_kernel<<<NCTA, NTHR, SMEM_BYTES>>>(
        (const float*)d_in[0],   // x
        (const float*)d_in[1],   // W_ih_l0
        (const float*)d_in[2],   // W_hh_l0
        (const float*)d_in[3],   // b_ih_l0
        (const float*)d_in[4],   // b_hh_l0
        (const float*)d_in[5],   // W_ih_l1
        (const float*)d_in[6],   // W_hh_l1
        (const float*)d_in[7],   // b_ih_l1
        (const float*)d_in[8],   // b_hh_l1
        (const float*)d_in[9],   // fc_w
        (const float*)d_in[10],  // fc_b
        (float*)d_out);
}

// round 4
// speedup vs baseline: 1.4712x; 1.0069x over previous
#include <cuda_runtime.h>

typedef unsigned long long ull;

#define SEQ   512
#define HD    64
#define G4    256          // 4*H
#define ROWS  16           // batch rows per CTA
#define NCTA  128          // 2048 / 16
#define NTHR  256
#define OUTF  72
#define XP    18           // Xd pitch in ull (16B-aligned, bank-rotating)

// SMEM: W0s[64][256] | W1s[128][256] (f32, gate-interleaved cols)
//       Xd: h0 buf0 [64][XP] | h0 buf1 [64][XP] | h1 [64][XP] | pad [2][XP]
// Tail pad absorbs the software-pipeline prefetch over-reads (k+2/k+3 at loop end).
#define XD_ROWS (3*64 + 2)
#define SMEM_BYTES ((64*G4 + 128*G4)*4 + XD_ROWS*XP*8)   // 224544

__device__ __forceinline__ ull pack2(float a, float b) {
    ull r; asm("mov.b64 %0, {%1, %2};" : "=l"(r) : "f"(a), "f"(b)); return r;
}
__device__ __forceinline__ void unpack2(ull v, float &a, float &b) {
    asm("mov.b64 {%0, %1}, %2;" : "=f"(a), "=f"(b) : "l"(v));
}
__device__ __forceinline__ void fma2(ull &d, ull a, ull b) {
    asm("fma.rn.f32x2 %0, %1, %2, %0;" : "+l"(d) : "l"(a), "l"(b));
}
__device__ __forceinline__ float sigf(float x) {
    return __fdividef(1.0f, 1.0f + __expf(-x));
}
__device__ __forceinline__ float tanhf_(float x) {
    float e = __expf(-2.0f * fabsf(x));
    float r = __fdividef(1.0f - e, 1.0f + e);
    return copysignf(r, x);
}
__device__ __forceinline__ float cell_update(ull aIF, ull aGO, float &c) {
    float gi, gf, gg, go;
    unpack2(aIF, gi, gf);
    unpack2(aGO, gg, go);
    float i = sigf(gi), f = sigf(gf), g = tanhf_(gg), o = sigf(go);
    c = f * c + i * g;
    return o * tanhf_(c);
}

// 8 packed FMAs: one k-slice into the 8 accumulators
#define FMA8(hA, hB, wv)                                     \
    do {                                                     \
        fma2(aIF0, (hA).x, (wv).x); fma2(aGO0, (hA).x, (wv).y); \
        fma2(aIF1, (hA).y, (wv).x); fma2(aGO1, (hA).y, (wv).y); \
        fma2(aIF2, (hB).x, (wv).x); fma2(aGO2, (hB).x, (wv).y); \
        fma2(aIF3, (hB).y, (wv).x); fma2(aGO3, (hB).y, (wv).y); \
    } while (0)

// Distance-2 software-pipelined GEMM over NK k-slices.
// Hbase: ull* (dup-packed h, pitch XP). Wbase: float* (gate-interleaved, pitch G4).
// Over-reads 2 k-slices past the end (in-bounds garbage, discarded).
#define GEMM_PIPE(Hbase, Wbase, NK)                                             \
    do {                                                                        \
        const ull*   Hp = (Hbase);                                              \
        const float* Wp = (Wbase);                                              \
        ulonglong2 h0A = *(const ulonglong2*)&Hp[0 * XP + gr0];                 \
        ulonglong2 h2A = *(const ulonglong2*)&Hp[0 * XP + gr0 + 2];             \
        ulonglong2 wA  = *(const ulonglong2*)&Wp[0 * G4 + jc4];                 \
        ulonglong2 h0B = *(const ulonglong2*)&Hp[1 * XP + gr0];                 \
        ulonglong2 h2B = *(const ulonglong2*)&Hp[1 * XP + gr0 + 2];             \
        ulonglong2 wB  = *(const ulonglong2*)&Wp[1 * G4 + jc4];                 \
        _Pragma("unroll 8")                                                     \
        for (int k = 0; k < (NK); k += 2) {                                     \
            ulonglong2 nh0A = *(const ulonglong2*)&Hp[(k + 2) * XP + gr0];      \
            ulonglong2 nh2A = *(const ulonglong2*)&Hp[(k + 2) * XP + gr0 + 2];  \
            ulonglong2 nwA  = *(const ulonglong2*)&Wp[(k + 2) * G4 + jc4];      \
            ulonglong2 nh0B = *(const ulonglong2*)&Hp[(k + 3) * XP + gr0];      \
            ulonglong2 nh2B = *(const ulonglong2*)&Hp[(k + 3) * XP + gr0 + 2];  \
            ulonglong2 nwB  = *(const ulonglong2*)&Wp[(k + 3) * G4 + jc4];      \
            FMA8(h0A, h2A, wA);                                                 \
            FMA8(h0B, h2B, wB);                                                 \
            h0A = nh0A; h2A = nh2A; wA = nwA;                                   \
            h0B = nh0B; h2B = nh2B; wB = nwB;                                   \
        }                                                                       \
    } while (0)

__global__ __launch_bounds__(NTHR, 1)
void lstm_forecaster_kernel(const float* __restrict__ x,
                            const float* __restrict__ Wih0,
                            const float* __restrict__ Whh0,
                            const float* __restrict__ bih0,
                            const float* __restrict__ bhh0,
                            const float* __restrict__ Wih1,
                            const float* __restrict__ Whh1,
                            const float* __restrict__ bih1,
                            const float* __restrict__ bhh1,
                            const float* __restrict__ fcw,
                            const float* __restrict__ fcb,
                            float* __restrict__ out)
{
    extern __shared__ float sm[];
    float* W0s = sm;                           // [64][256]  gate-interleaved, k-major
    float* W1s = sm + 64 * G4;                 // [128][256] k<64: Wih1, k>=64: Whh1
    ull*   Xd  = (ull*)(sm + (64 + 128) * G4); // [XD_ROWS][XP]

    const int tid  = threadIdx.x;
    const int warp = tid >> 5, lane = tid & 31;
    const int rr   = lane >> 3;               // row-group 0..3
    const int gg   = lane & 7;                // cell-within-warp 0..7
    const int j    = warp * 8 + gg;           // cell index 0..63
    const int jc4  = j << 2;                  // first interleaved col of cell j
    const int gr0  = rr << 2;                 // first of 4 rows

    // ---- weights into shared, gate-interleaved: col' = cell*4 + gate ----
    for (int idx = tid; idx < 64 * G4; idx += NTHR) {
        int k = idx >> 8, col = idx & 255;
        int jj = col >> 2, g = col & 3;
        W0s[idx] = Whh0[(g * HD + jj) * HD + k];
    }
    for (int idx = tid; idx < 128 * G4; idx += NTHR) {
        int k = idx >> 8, col = idx & 255;
        int jj = col >> 2, g = col & 3;
        W1s[idx] = (k < HD) ? Wih1[(g * HD + jj) * HD + k]
                            : Whh1[(g * HD + jj) * HD + (k - HD)];
    }
    for (int idx = tid; idx < XD_ROWS * XP; idx += NTHR) Xd[idx] = 0ull;

    // ---- per-thread constants for cell j ----
    ull w0if = pack2(Wih0[j],          Wih0[j + HD]);
    ull w0go = pack2(Wih0[j + 2*HD],   Wih0[j + 3*HD]);
    ull b0if = pack2(bih0[j] + bhh0[j],               bih0[j + HD] + bhh0[j + HD]);
    ull b0go = pack2(bih0[j + 2*HD] + bhh0[j + 2*HD], bih0[j + 3*HD] + bhh0[j + 3*HD]);
    ull b1if = pack2(bih1[j] + bhh1[j],               bih1[j + HD] + bhh1[j + HD]);
    ull b1go = pack2(bih1[j + 2*HD] + bhh1[j + 2*HD], bih1[j + 3*HD] + bhh1[j + 3*HD]);

    float c0[4] = {0.f, 0.f, 0.f, 0.f};
    float c1[4] = {0.f, 0.f, 0.f, 0.f};

    ull* X0a = Xd + 64 * XP;   // read at s=0 (zeros)
    ull* X0b = Xd;             // written at s=0
    ull* X1  = Xd + 2 * 64 * XP;

    const int gRow = blockIdx.x * ROWS;

    float xr0 = x[(gRow + gr0 + 0) * SEQ];
    float xr1 = x[(gRow + gr0 + 1) * SEQ];
    float xr2 = x[(gRow + gr0 + 2) * SEQ];
    float xr3 = x[(gRow + gr0 + 3) * SEQ];

    __syncthreads();

    for (int s = 0; s < SEQ; ++s) {
        ull* X0r = X0a;   // h0(s-1)
        ull* X0w = X0b;   // receives h0(s)

        // ============ layer 0: gates = b0 + x*wih0 + h0(s-1) @ Whh0^T ============
        ull aIF0 = b0if, aGO0 = b0go, aIF1 = b0if, aGO1 = b0go;
        ull aIF2 = b0if, aGO2 = b0go, aIF3 = b0if, aGO3 = b0go;
        {
            ull xx0 = pack2(xr0, xr0), xx1 = pack2(xr1, xr1);
            ull xx2 = pack2(xr2, xr2), xx3 = pack2(xr3, xr3);
            fma2(aIF0, xx0, w0if); fma2(aGO0, xx0, w0go);
            fma2(aIF1, xx1, w0if); fma2(aGO1, xx1, w0go);
            fma2(aIF2, xx2, w0if); fma2(aGO2, xx2, w0go);
            fma2(aIF3, xx3, w0if); fma2(aGO3, xx3, w0go);
        }
        int sn = (s + 1 < SEQ) ? (s + 1) : s;
        float xn0 = x[(gRow + gr0 + 0) * SEQ + sn];
        float xn1 = x[(gRow + gr0 + 1) * SEQ + sn];
        float xn2 = x[(gRow + gr0 + 2) * SEQ + sn];
        float xn3 = x[(gRow + gr0 + 3) * SEQ + sn];

        GEMM_PIPE(X0r, W0s, HD);

        xr0 = xn0; xr1 = xn1; xr2 = xn2; xr3 = xn3;

        // ============ layer 0 state update -> h0(s) into X0w (double buffer) ============
        {
            float h0 = cell_update(aIF0, aGO0, c0[0]);
            float h1 = cell_update(aIF1, aGO1, c0[1]);
            float h2 = cell_update(aIF2, aGO2, c0[2]);
            float h3 = cell_update(aIF3, aGO3, c0[3]);
            *(ulonglong2*)&X0w[j * XP + gr0]     = make_ulonglong2(pack2(h0, h0), pack2(h1, h1));
            *(ulonglong2*)&X0w[j * XP + gr0 + 2] = make_ulonglong2(pack2(h2, h2), pack2(h3, h3));
        }
        __syncthreads();   // h0(s) + h1(s-1) visible to all

        // ============ layer 1: gates = b1 + h0(s)@Wih1^T + h1(s-1)@Whh1^T ============
        aIF0 = b1if; aGO0 = b1go; aIF1 = b1if; aGO1 = b1go;
        aIF2 = b1if; aGO2 = b1go; aIF3 = b1if; aGO3 = b1go;

        GEMM_PIPE(X0w, W1s, HD);
        GEMM_PIPE(X1,  W1s + HD * G4, HD);

        __syncthreads();   // WAR: all h1(s-1) reads done before overwrite

        // ============ layer 1 state update -> h1(s) (overlaps next L0 GEMM) ============
        {
            float h0 = cell_update(aIF0, aGO0, c1[0]);
            float h1 = cell_update(aIF1, aGO1, c1[1]);
            float h2 = cell_update(aIF2, aGO2, c1[2]);
            float h3 = cell_update(aIF3, aGO3, c1[3]);
            *(ulonglong2*)&X1[j * XP + gr0]     = make_ulonglong2(pack2(h0, h0), pack2(h1, h1));
            *(ulonglong2*)&X1[j * XP + gr0 + 2] = make_ulonglong2(pack2(h2, h2), pack2(h3, h3));
        }

        ull* t = X0a; X0a = X0b; X0b = t;
    }

    __syncthreads();

    // ============ final FC: out = h1_last @ fcw^T + fcb ============
    const float* H1 = (const float*)(Xd + 2 * 64 * XP);
    for (int idx = tid; idx < ROWS * OUTF; idx += NTHR) {
        int r = idx / OUTF;
        int o = idx - r * OUTF;
        float acc = fcb[o];
        #pragma unroll 16
        for (int k = 0; k < HD; ++k) {
            float h = H1[(k * XP + r) * 2];
            acc = fmaf(h, fcw[o * HD + k], acc);
        }
        out[(gRow + r) * OUTF + o] = acc;
    }
}

extern "C" void kernel_launch(void* const* d_in, const int* in_sizes, int n_in,
                              void* d_out, int out_size)
{
    (void)in_sizes; (void)n_in; (void)out_size;
    cudaFuncSetAttribute(lstm_forecaster_kernel,
                         cudaFuncAttributeMaxDynamicSharedMemorySize, SMEM_BYTES);
    lstm_forecaster_kernel<<<NCTA, NTHR, SMEM_BYTES>>>(
        (const float*)d_in[0],   // x
        (const float*)d_in[1],   // W_ih_l0
        (const float*)d_in[2],   // W_hh_l0
        (const float*)d_in[3],   // b_ih_l0
        (const float*)d_in[4],   // b_hh_l0
        (const float*)d_in[5],   // W_ih_l1
        (const float*)d_in[6],   // W_hh_l1
        (const float*)d_in[7],   // b_ih_l1
        (const float*)d_in[8],   // b_hh_l1
        (const float*)d_in[9],   // fc_w
        (const float*)d_in[10],  // fc_b
        (float*)d_out);
}